// round 8
// baseline (speedup 1.0000x reference)
#include <cuda_runtime.h>
#include <cuda_bf16.h>

#define BATCH 256
#define NPOS 4
#define NNEG 1024
#define DIM 512
#define ROW4 (DIM / 4)                            // 128 float4 per row
#define CHUNKS 4
#define ROWS_PER_CHUNK (NNEG / CHUNKS)            // 256
#define WARPS_B 8
#define ROWS_PER_WARP (ROWS_PER_CHUNK / WARPS_B)  // 32
#define RGROUP 4                                  // rows per warp-iteration (1 per 8-lane group)
#define ITERS (ROWS_PER_WARP / RGROUP)            // 8
#define NBLOCKS (BATCH * CHUNKS)                  // 1024
#define EPS_F 1e-8f
#define INV_T 10.0f

// Scratch (device allocation forbidden) — fully rewritten each launch.
__device__ float g_pos_sim[BATCH * NPOS];
__device__ float g_exp_part[NBLOCKS];
__device__ int4  g_cnt_part[NBLOCKS];
__device__ unsigned int g_ticket = 0;   // reset by the finalizing block each launch

__device__ __forceinline__ float4 ldcs4(const float4* p) { return __ldcs(p); }

// ---------------------------------------------------------------------------
// Single fused kernel.  One block per (b, chunk); 256 negative rows per block.
// Row geometry: each 8-lane group owns ONE row per iteration (4 rows/warp/iter).
//   - every LDG.128 still covers 4 full 128B lines (fully coalesced)
//   - cross-lane reduction is 3 shuffle levels for all 4 rows at once
//     (6 SHFLs/iter instead of 40) -> much shorter post-load serial tail
//   - anchor lives in shared memory (broadcast LDS, conflict-free)
// Pipeline per warp: issue 16 LDG -> (first iter: prologue overlapped) ->
// consume -> issue next 16 LDG -> 3-level shuffles + MUFU tail.
// Epilogue: block partial -> global; last block (ticket) finalizes.
// ---------------------------------------------------------------------------
__global__ void __launch_bounds__(256) rrl_fused_kernel(const float* __restrict__ anchor,
                                                        const float* __restrict__ positives,
                                                        const float* __restrict__ negatives,
                                                        float* __restrict__ out) {
    const int b       = blockIdx.x >> 2;
    const int chunk   = blockIdx.x & 3;
    const int w       = threadIdx.x >> 5;
    const int lane    = threadIdx.x & 31;
    const int row_sub = lane >> 3;      // which row of the group-of-4
    const int seg     = lane & 7;       // 8-lane segment within the row

    __shared__ float4 s_anchor[ROW4];   // 2 KB
    __shared__ float  s_pos[NPOS];
    __shared__ float  s_rinv;
    __shared__ float  s_exp[WARPS_B];
    __shared__ int    s_cnt[WARPS_B][NPOS];
    __shared__ int    s_last;

    const float4* neg_base = reinterpret_cast<const float4*>(
        negatives + ((size_t)b * NNEG + chunk * ROWS_PER_CHUNK + w * ROWS_PER_WARP) * DIM);

    // ---- (1) issue the first streaming batch IMMEDIATELY ----
    // iteration 0 rows: row_sub;  lane loads float4s at index seg + 8k of its row
    float4 v[16];
#pragma unroll
    for (int k = 0; k < 16; k++)
        v[k] = ldcs4(neg_base + (size_t)row_sub * ROW4 + seg + 8 * k);

    // ---- (2) prologue overlapped with the in-flight loads ----
    // anchor -> smem (threads 0..127, one float4 each)
    if (threadIdx.x < ROW4) {
        s_anchor[threadIdx.x] =
            reinterpret_cast<const float4*>(anchor + (size_t)b * DIM)[threadIdx.x];
    }
    __syncthreads();

    if (w < NPOS) {
        float4 af[4];
#pragma unroll
        for (int k = 0; k < 4; k++) af[k] = s_anchor[lane + 32 * k];
        const float4* p4 =
            reinterpret_cast<const float4*>(positives + ((size_t)b * NPOS + w) * DIM);
        float dot = 0.f, sqa = 0.f, sqp = 0.f;
#pragma unroll
        for (int k = 0; k < 4; k++) {
            float4 pv = p4[lane + 32 * k];
            dot += af[k].x * pv.x + af[k].y * pv.y + af[k].z * pv.z + af[k].w * pv.w;
            sqa += af[k].x * af[k].x + af[k].y * af[k].y + af[k].z * af[k].z + af[k].w * af[k].w;
            sqp += pv.x * pv.x + pv.y * pv.y + pv.z * pv.z + pv.w * pv.w;
        }
#pragma unroll
        for (int o = 16; o; o >>= 1) {
            dot += __shfl_xor_sync(0xffffffffu, dot, o);
            sqa += __shfl_xor_sync(0xffffffffu, sqa, o);
            sqp += __shfl_xor_sync(0xffffffffu, sqp, o);
        }
        if (lane == 0) {
            const float na = sqrtf(sqa);
            const float sim = dot / fmaxf(na * sqrtf(sqp), EPS_F);
            s_pos[w] = sim;
            if (w == 0) s_rinv = 1.0f / na;
            if (chunk == 0) g_pos_sim[b * NPOS + w] = sim;
        }
    }
    __syncthreads();

    const float rinv_a = s_rinv;
    const float t0 = s_pos[0], t1 = s_pos[1], t2 = s_pos[2], t3 = s_pos[3];

    float sum_exp = 0.f;
    int c0 = 0, c1 = 0, c2 = 0, c3 = 0;

    // ---- (3) software-pipelined streaming loop ----
    for (int i = 0; i < ITERS; i++) {
        // consume v: 4 independent FFMA chains each for dot and sq (ILP)
        float d0 = 0.f, d1 = 0.f, d2 = 0.f, d3 = 0.f;
        float q0 = 0.f, q1 = 0.f, q2 = 0.f, q3 = 0.f;
#pragma unroll
        for (int k = 0; k < 16; k += 4) {
            const float4 a0 = s_anchor[seg + 8 * (k + 0)];
            const float4 a1 = s_anchor[seg + 8 * (k + 1)];
            const float4 a2 = s_anchor[seg + 8 * (k + 2)];
            const float4 a3 = s_anchor[seg + 8 * (k + 3)];
            d0 += a0.x * v[k+0].x + a0.y * v[k+0].y + a0.z * v[k+0].z + a0.w * v[k+0].w;
            d1 += a1.x * v[k+1].x + a1.y * v[k+1].y + a1.z * v[k+1].z + a1.w * v[k+1].w;
            d2 += a2.x * v[k+2].x + a2.y * v[k+2].y + a2.z * v[k+2].z + a2.w * v[k+2].w;
            d3 += a3.x * v[k+3].x + a3.y * v[k+3].y + a3.z * v[k+3].z + a3.w * v[k+3].w;
            q0 += v[k+0].x * v[k+0].x + v[k+0].y * v[k+0].y + v[k+0].z * v[k+0].z + v[k+0].w * v[k+0].w;
            q1 += v[k+1].x * v[k+1].x + v[k+1].y * v[k+1].y + v[k+1].z * v[k+1].z + v[k+1].w * v[k+1].w;
            q2 += v[k+2].x * v[k+2].x + v[k+2].y * v[k+2].y + v[k+2].z * v[k+2].z + v[k+2].w * v[k+2].w;
            q3 += v[k+3].x * v[k+3].x + v[k+3].y * v[k+3].y + v[k+3].z * v[k+3].z + v[k+3].w * v[k+3].w;
        }

        // issue next batch's loads NOW — in flight through the whole tail
        if (i + 1 < ITERS) {
            const size_t row = (size_t)((i + 1) * RGROUP + row_sub) * ROW4;
#pragma unroll
            for (int k = 0; k < 16; k++)
                v[k] = ldcs4(neg_base + row + seg + 8 * k);
        }

        float dot = (d0 + d1) + (d2 + d3);
        float sq  = (q0 + q1) + (q2 + q3);

        // 3-level reduction within each 8-lane group (reduces all 4 rows at once)
#pragma unroll
        for (int o = 4; o; o >>= 1) {
            dot += __shfl_xor_sync(0xffffffffu, dot, o);
            sq  += __shfl_xor_sync(0xffffffffu, sq, o);
        }

        // tail (computed redundantly in all 8 lanes of the group — uniform)
        const float sim = dot * (rinv_a * rsqrtf(fmaxf(sq, EPS_F * EPS_F)));
        sum_exp += __expf(sim * INV_T);
        c0 += (sim > t0);
        c1 += (sim > t1);
        c2 += (sim > t2);
        c3 += (sim > t3);
    }

    // ---- warp-level final reduction (each row was counted 8x) ----
#pragma unroll
    for (int o = 16; o; o >>= 1) {
        sum_exp += __shfl_xor_sync(0xffffffffu, sum_exp, o);
        c0 += __shfl_xor_sync(0xffffffffu, c0, o);
        c1 += __shfl_xor_sync(0xffffffffu, c1, o);
        c2 += __shfl_xor_sync(0xffffffffu, c2, o);
        c3 += __shfl_xor_sync(0xffffffffu, c3, o);
    }
    if (lane == 0) {
        s_exp[w]    = sum_exp * 0.125f;   // exact /8
        s_cnt[w][0] = c0 >> 3;            // exact /8
        s_cnt[w][1] = c1 >> 3;
        s_cnt[w][2] = c2 >> 3;
        s_cnt[w][3] = c3 >> 3;
    }
    __syncthreads();
    if (threadIdx.x == 0) {
        float se = 0.f;
        int k0 = 0, k1 = 0, k2 = 0, k3 = 0;
#pragma unroll
        for (int j = 0; j < WARPS_B; j++) {
            se += s_exp[j];
            k0 += s_cnt[j][0]; k1 += s_cnt[j][1]; k2 += s_cnt[j][2]; k3 += s_cnt[j][3];
        }
        g_exp_part[blockIdx.x] = se;
        g_cnt_part[blockIdx.x] = make_int4(k0, k1, k2, k3);
        __threadfence();                       // partials visible before ticket
        const unsigned int t = atomicAdd(&g_ticket, 1u);
        s_last = (t == NBLOCKS - 1u) ? 1 : 0;
    }
    __syncthreads();

    // ---- last block finalizes (deterministic fixed-order fold) ----
    if (s_last) {
        const int bb = threadIdx.x;            // thread = batch index

        float se = 0.f;
        int cnt[NPOS] = {0, 0, 0, 0};
#pragma unroll
        for (int c = 0; c < CHUNKS; c++) {
            const int idx = bb * CHUNKS + c;
            se += g_exp_part[idx];
            const int4 k = g_cnt_part[idx];
            cnt[0] += k.x; cnt[1] += k.y; cnt[2] += k.z; cnt[3] += k.w;
        }

        float ps[NPOS], ep[NPOS];
        float denom = se;
#pragma unroll
        for (int p = 0; p < NPOS; p++) {
            ps[p] = g_pos_sim[bb * NPOS + p];
            ep[p] = expf(ps[p] * INV_T);
            denom += ep[p];
        }

        float err = 0.f, psum = 0.f;
#pragma unroll
        for (int p = 0; p < NPOS; p++) {
            int rank = cnt[p];
#pragma unroll
            for (int q = 0; q < NPOS; q++) {
                if (ps[q] > ps[p]) rank++;
                else if (q < p && ps[q] == ps[p]) rank++;
            }
            err  += (ep[p] / denom) / (float)(rank + 1);
            psum += ps[p];
        }

        __shared__ float s_err[256];
        __shared__ float s_psum[256];
        s_err[bb]  = err;
        s_psum[bb] = psum;
        __syncthreads();
        for (int off = 128; off; off >>= 1) {
            if (bb < off) {
                s_err[bb]  += s_err[bb + off];
                s_psum[bb] += s_psum[bb + off];
            }
            __syncthreads();
        }
        if (bb == 0) {
            out[0] = -s_err[0] / (float)BATCH +
                     0.3f * (1.0f - s_psum[0] / (float)(BATCH * NPOS));
            g_ticket = 0;                      // re-arm for next (graph) replay
        }
    }
}

// ---------------------------------------------------------------------------
extern "C" void kernel_launch(void* const* d_in, const int* in_sizes, int n_in,
                              void* d_out, int out_size) {
    const float* anchor    = (const float*)d_in[0];
    const float* positives = (const float*)d_in[1];
    const float* negatives = (const float*)d_in[2];

    rrl_fused_kernel<<<NBLOCKS, 256>>>(anchor, positives, negatives, (float*)d_out);
}

// round 9
// speedup vs baseline: 1.0431x; 1.0431x over previous
#include <cuda_runtime.h>
#include <cuda_bf16.h>

#define BATCH 256
#define NPOS 4
#define NNEG 1024
#define DIM 512
#define ROW4 (DIM / 4)                            // 128 float4 per row
#define CHUNKS 8
#define ROWS_PER_CHUNK (NNEG / CHUNKS)            // 128
#define WARPS_B 8
#define ROWS_PER_WARP (ROWS_PER_CHUNK / WARPS_B)  // 16
#define RBATCH 4
#define ITERS (ROWS_PER_WARP / RBATCH)            // 4
#define NITEMS (BATCH * CHUNKS)                   // 2048
#define GRIDB 296                                 // 2 CTAs/SM, all resident
#define EPS_F 1e-8f
#define INV_T 10.0f

// Scratch (device allocation forbidden) — fully rewritten each launch.
__device__ float g_pos_sim[BATCH * NPOS];
__device__ float g_exp_part[NITEMS];
__device__ int4  g_cnt_part[NITEMS];
__device__ unsigned int g_ticket = 0;   // reset by the finalizing block each launch

__device__ __forceinline__ float4 ldcs4(const float4* p) { return __ldcs(p); }

// ---------------------------------------------------------------------------
// Persistent-CTA fused kernel.  296 blocks, each strides over ~7 work items
// (item = (b, chunk of 128 negative rows)).  The global-load stream is kept
// continuous ACROSS item boundaries: the last streaming iteration of item i
// issues the first 16 LDG.128 of item i+1, so the per-item prologue (anchor
// reload, pos_sim, thresholds) and the per-item fold both execute while loads
// are in flight.  Row geometry = proven R6 layout: warp-per-row, RBATCH=4,
// anchor register-resident, interleaved butterfly reductions.
// Finalization: global ticket; the last block folds all partials in a fixed
// deterministic order and writes the scalar loss.
// ---------------------------------------------------------------------------
__global__ void __launch_bounds__(256) rrl_persist_kernel(const float* __restrict__ anchor,
                                                          const float* __restrict__ positives,
                                                          const float* __restrict__ negatives,
                                                          float* __restrict__ out) {
    const int w    = threadIdx.x >> 5;
    const int lane = threadIdx.x & 31;

    __shared__ float s_pos[NPOS];
    __shared__ float s_rinv;
    __shared__ float s_exp[WARPS_B];
    __shared__ int   s_cnt[WARPS_B][NPOS];
    __shared__ int   s_last;

    int item = blockIdx.x;

    // per-warp base pointer for an item's streaming region
    auto neg_ptr = [&](int it) {
        const int b = it >> 3, ch = it & 7;
        return reinterpret_cast<const float4*>(
            negatives + ((size_t)b * NNEG + ch * ROWS_PER_CHUNK + w * ROWS_PER_WARP) * DIM);
    };

    // ---- prime the pipeline: first item's first batch ----
    const float4* nb = nullptr;
    float4 v[RBATCH][4];
    if (item < NITEMS) {
        nb = neg_ptr(item);
#pragma unroll
        for (int r = 0; r < RBATCH; r++)
#pragma unroll
            for (int k = 0; k < 4; k++)
                v[r][k] = ldcs4(nb + (size_t)r * ROW4 + lane + 32 * k);
    }

    while (item < NITEMS) {
        const int b = item >> 3;
        const int chunk = item & 7;

        // ---- prologue (overlapped with the in-flight streaming loads) ----
        const float4* a4 = reinterpret_cast<const float4*>(anchor + (size_t)b * DIM);
        float4 af[4];
#pragma unroll
        for (int k = 0; k < 4; k++) af[k] = a4[lane + 32 * k];

        if (w < NPOS) {
            const float4* p4 =
                reinterpret_cast<const float4*>(positives + ((size_t)b * NPOS + w) * DIM);
            float dot = 0.f, sqa = 0.f, sqp = 0.f;
#pragma unroll
            for (int k = 0; k < 4; k++) {
                float4 pv = p4[lane + 32 * k];
                dot += af[k].x * pv.x + af[k].y * pv.y + af[k].z * pv.z + af[k].w * pv.w;
                sqa += af[k].x * af[k].x + af[k].y * af[k].y + af[k].z * af[k].z + af[k].w * af[k].w;
                sqp += pv.x * pv.x + pv.y * pv.y + pv.z * pv.z + pv.w * pv.w;
            }
#pragma unroll
            for (int o = 16; o; o >>= 1) {
                dot += __shfl_xor_sync(0xffffffffu, dot, o);
                sqa += __shfl_xor_sync(0xffffffffu, sqa, o);
                sqp += __shfl_xor_sync(0xffffffffu, sqp, o);
            }
            if (lane == 0) {
                const float na = sqrtf(sqa);
                const float sim = dot / fmaxf(na * sqrtf(sqp), EPS_F);
                s_pos[w] = sim;
                if (w == 0) s_rinv = 1.0f / na;
                if (chunk == 0) g_pos_sim[b * NPOS + w] = sim;
            }
        }
        __syncthreads();    // #1: s_pos / s_rinv ready

        const float rinv_a = s_rinv;
        const float t0 = s_pos[0], t1 = s_pos[1], t2 = s_pos[2], t3 = s_pos[3];

        const int next_item = item + GRIDB;
        const float4* nb_next = (next_item < NITEMS) ? neg_ptr(next_item) : nullptr;

        float sum_exp = 0.f;
        int c0 = 0, c1 = 0, c2 = 0, c3 = 0;

        // ---- streaming loop (cross-item pipelined) ----
        for (int i = 0; i < ITERS; i++) {
            // consume v into per-lane partials (frees the v registers)
            float dot[RBATCH], sq[RBATCH];
#pragma unroll
            for (int r = 0; r < RBATCH; r++) {
                float d = 0.f, s = 0.f;
#pragma unroll
                for (int k = 0; k < 4; k++) {
                    d += af[k].x * v[r][k].x + af[k].y * v[r][k].y +
                         af[k].z * v[r][k].z + af[k].w * v[r][k].w;
                    s += v[r][k].x * v[r][k].x + v[r][k].y * v[r][k].y +
                         v[r][k].z * v[r][k].z + v[r][k].w * v[r][k].w;
                }
                dot[r] = d;
                sq[r]  = s;
            }

            // issue the NEXT batch immediately: same item, or first batch of
            // the next item (keeps the LDG stream continuous across items)
            if (i + 1 < ITERS) {
#pragma unroll
                for (int r = 0; r < RBATCH; r++)
#pragma unroll
                    for (int k = 0; k < 4; k++)
                        v[r][k] = ldcs4(nb + (size_t)((i + 1) * RBATCH + r) * ROW4 + lane + 32 * k);
            } else if (nb_next) {
#pragma unroll
                for (int r = 0; r < RBATCH; r++)
#pragma unroll
                    for (int k = 0; k < 4; k++)
                        v[r][k] = ldcs4(nb_next + (size_t)r * ROW4 + lane + 32 * k);
            }

            // interleaved butterfly reductions (8 independent chains per level)
#pragma unroll
            for (int o = 16; o; o >>= 1) {
#pragma unroll
                for (int r = 0; r < RBATCH; r++) {
                    dot[r] += __shfl_xor_sync(0xffffffffu, dot[r], o);
                    sq[r]  += __shfl_xor_sync(0xffffffffu, sq[r], o);
                }
            }

            // sim tail (uniform across lanes)
#pragma unroll
            for (int r = 0; r < RBATCH; r++) {
                const float sim = dot[r] * (rinv_a * rsqrtf(fmaxf(sq[r], EPS_F * EPS_F)));
                sum_exp += __expf(sim * INV_T);
                c0 += (sim > t0);
                c1 += (sim > t1);
                c2 += (sim > t2);
                c3 += (sim > t3);
            }
        }

        // ---- per-item fold (next item's loads already in flight) ----
        if (lane == 0) {
            s_exp[w]    = sum_exp;
            s_cnt[w][0] = c0; s_cnt[w][1] = c1; s_cnt[w][2] = c2; s_cnt[w][3] = c3;
        }
        __syncthreads();    // #2: partials ready (also fences s_pos reuse)
        if (threadIdx.x == 0) {
            float se = 0.f;
            int k0 = 0, k1 = 0, k2 = 0, k3 = 0;
#pragma unroll
            for (int j = 0; j < WARPS_B; j++) {
                se += s_exp[j];
                k0 += s_cnt[j][0]; k1 += s_cnt[j][1]; k2 += s_cnt[j][2]; k3 += s_cnt[j][3];
            }
            g_exp_part[item] = se;
            g_cnt_part[item] = make_int4(k0, k1, k2, k3);
        }

        item = next_item;
        nb = nb_next;
    }

    // ---- block done: ticket; last block finalizes ----
    if (threadIdx.x == 0) {
        __threadfence();                     // all partial STGs visible
        const unsigned int t = atomicAdd(&g_ticket, 1u);
        s_last = (t == GRIDB - 1u) ? 1 : 0;
    }
    __syncthreads();

    if (s_last) {
        const int bb = threadIdx.x;          // thread = batch index

        float se = 0.f;
        int cnt[NPOS] = {0, 0, 0, 0};
#pragma unroll
        for (int c = 0; c < CHUNKS; c++) {
            const int idx = bb * CHUNKS + c;
            se += g_exp_part[idx];
            const int4 k = g_cnt_part[idx];
            cnt[0] += k.x; cnt[1] += k.y; cnt[2] += k.z; cnt[3] += k.w;
        }

        float ps[NPOS], ep[NPOS];
        float denom = se;
#pragma unroll
        for (int p = 0; p < NPOS; p++) {
            ps[p] = g_pos_sim[bb * NPOS + p];
            ep[p] = expf(ps[p] * INV_T);
            denom += ep[p];
        }

        float err = 0.f, psum = 0.f;
#pragma unroll
        for (int p = 0; p < NPOS; p++) {
            int rank = cnt[p];
#pragma unroll
            for (int q = 0; q < NPOS; q++) {
                if (ps[q] > ps[p]) rank++;
                else if (q < p && ps[q] == ps[p]) rank++;
            }
            err  += (ep[p] / denom) / (float)(rank + 1);
            psum += ps[p];
        }

        __shared__ float s_err[256];
        __shared__ float s_psum[256];
        s_err[bb]  = err;
        s_psum[bb] = psum;
        __syncthreads();
        for (int off = 128; off; off >>= 1) {
            if (bb < off) {
                s_err[bb]  += s_err[bb + off];
                s_psum[bb] += s_psum[bb + off];
            }
            __syncthreads();
        }
        if (bb == 0) {
            out[0] = -s_err[0] / (float)BATCH +
                     0.3f * (1.0f - s_psum[0] / (float)(BATCH * NPOS));
            g_ticket = 0;                    // re-arm for next (graph) replay
        }
    }
}

// ---------------------------------------------------------------------------
extern "C" void kernel_launch(void* const* d_in, const int* in_sizes, int n_in,
                              void* d_out, int out_size) {
    const float* anchor    = (const float*)d_in[0];
    const float* positives = (const float*)d_in[1];
    const float* negatives = (const float*)d_in[2];

    rrl_persist_kernel<<<GRIDB, 256>>>(anchor, positives, negatives, (float*)d_out);
}